// round 10
// baseline (speedup 1.0000x reference)
#include <cuda_runtime.h>
#include <cuda_fp16.h>
#include <math.h>
#include <stdint.h>

#define D        64
#define BM       128
#define KCODES   1024
#define CHUNK    128
#define NCHUNKS  (KCODES / CHUNK)
#define TPB      256
#define PAD      72      // halves per row (144B rows: ldmatrix conflict-free)

// SMEM byte offsets
#define OFF_C2     0        // 1024 f32
#define OFF_ROWN   4096     // 128 f32 row norms
#define OFF_BESTI  4608     // 128 i32
#define OFF_FBFLAG 5120     // 128 i32 fallback flags
#define OFF_WSUM   5696     // 8 f32
#define OFF_AHI    6144     // 128*72 half = 18432
#define OFF_ALO    24576    // 18432
#define OFF_B      43008    // hi-only chunk image: 18432
#define OFF_CAND   61440    // 128 rows * 8 slots * 4 cands * 8B = 32768
#define SMEM_TOTAL 94208

__device__ double g_mse_sum;
__device__ int    g_counts[1024];
__device__ float  g_c2[1024];
__device__ float  g_cmax;            // max |c|, plain store from vq_prep2
__device__ __align__(16) __half g_cbh[KCODES * PAD];

__device__ __forceinline__ uint32_t smem_u32(const void* p) {
    uint32_t a;
    asm("{ .reg .u64 t; cvta.to.shared.u64 t, %1; cvt.u32.u64 %0, t; }" : "=r"(a) : "l"(p));
    return a;
}
#define LDSM_X4(r0, r1, r2, r3, addr) \
    asm volatile("ldmatrix.sync.aligned.m8n8.x4.shared.b16 {%0,%1,%2,%3}, [%4];" \
        : "=r"(r0), "=r"(r1), "=r"(r2), "=r"(r3) : "r"(addr))
#define MMA16816(c, a, b0, b1) \
    asm volatile("mma.sync.aligned.m16n8k16.row.col.f32.f16.f16.f32 " \
        "{%0,%1,%2,%3}, {%4,%5,%6,%7}, {%8,%9}, {%0,%1,%2,%3};" \
        : "+f"((c)[0]), "+f"((c)[1]), "+f"((c)[2]), "+f"((c)[3]) \
        : "r"((a)[0]), "r"((a)[1]), "r"((a)[2]), "r"((a)[3]), "r"(b0), "r"(b1))

// sorted best-4 insert (v ascending); strict < keeps earliest on ties
__device__ __forceinline__ void ins4(float* v, int* ix, float d, int k) {
    if (d < v[3]) {
        if (d < v[1]) {
            v[3] = v[2]; ix[3] = ix[2];
            v[2] = v[1]; ix[2] = ix[1];
            if (d < v[0]) { v[1] = v[0]; ix[1] = ix[0]; v[0] = d; ix[0] = k; }
            else          { v[1] = d; ix[1] = k; }
        } else {
            if (d < v[2]) { v[3] = v[2]; ix[3] = ix[2]; v[2] = d; ix[2] = k; }
            else          { v[3] = d; ix[3] = k; }
        }
    }
}

// ---------------- prep: fp16 codebook image, |c|^2, zero accum ----------------
__global__ void vq_prep(const float* __restrict__ cb) {
    int k = blockIdx.x;     // code
    int d = threadIdx.x;    // 0..63
    float v = cb[k * D + d];
    g_cbh[k * PAD + d] = __float2half_rn(v);
    if (d < 8) g_cbh[k * PAD + 64 + d] = __half(0.f);
    float sq = v * v;
#pragma unroll
    for (int o = 16; o > 0; o >>= 1) sq += __shfl_down_sync(0xffffffffu, sq, o);
    __shared__ float s2[2];
    if ((d & 31) == 0) s2[d >> 5] = sq;
    __syncthreads();
    if (d == 0) g_c2[k] = s2[0] + s2[1];
    if (k == 0) {
        if (d == 0) g_mse_sum = 0.0;
        for (int i = d; i < 1024; i += 64) g_counts[i] = 0;
    }
}

// ---------------- prep2: cmax = max_k |c_k| (shuffle/shared reduce, plain store) ----------------
__global__ void vq_prep2() {
    const int tid = threadIdx.x;        // 1024 threads
    float m = g_c2[tid];
#pragma unroll
    for (int o = 16; o > 0; o >>= 1) m = fmaxf(m, __shfl_down_sync(0xffffffffu, m, o));
    __shared__ float ws[32];
    if ((tid & 31) == 0) ws[tid >> 5] = m;
    __syncthreads();
    if (tid == 0) {
        float mm = 0.f;
#pragma unroll
        for (int w = 0; w < 32; w++) mm = fmaxf(mm, ws[w]);
        g_cmax = sqrtf(mm);
    }
}

// ---------------- main ----------------
__global__ void __launch_bounds__(TPB)
vq_main(const float* __restrict__ x, const float* __restrict__ cb,
        int N, float* __restrict__ outQ, float* __restrict__ outT, int writeExtras)
{
    extern __shared__ char smc[];
    const uint32_t sb = smem_u32(smc);
    float*  c2s    = (float*)(smc + OFF_C2);
    float*  rowN   = (float*)(smc + OFF_ROWN);
    int*    bestI  = (int*)(smc + OFF_BESTI);
    int*    fbflag = (int*)(smc + OFF_FBFLAG);
    float*  wsum   = (float*)(smc + OFF_WSUM);
    __half* Ahi    = (__half*)(smc + OFF_AHI);
    __half* Alo    = (__half*)(smc + OFF_ALO);
    float4* Bv     = (float4*)(smc + OFF_B);
    uint2*  cand   = (uint2*)(smc + OFF_CAND);   // [row][slot][4]

    const int tid = threadIdx.x;
    const int warp = tid >> 5, lane = tid & 31;
    const int mblk = (warp & 3) * 32;
    const int nb   = warp >> 2;
    const int nblk = nb * 64;
    const int rowBase = blockIdx.x * BM;

    // x tile load + fp16 split
    for (int i = tid; i < BM * D; i += TPB) {
        int r = i >> 6, d = i & 63;
        int gr = rowBase + r; if (gr >= N) gr = N - 1;
        float v = x[(size_t)gr * D + d];
        __half hi = __float2half_rn(v);
        Ahi[r * PAD + d] = hi;
        Alo[r * PAD + d] = __float2half_rn(v - __half2float(hi));
    }
    for (int i = tid; i < 1024; i += TPB) c2s[i] = g_c2[i];
    __syncthreads();
    if (tid < BM) {    // row norms for margin
        float s = 0.f;
#pragma unroll
        for (int d = 0; d < D; d++) {
            float xv = __half2float(Ahi[tid * PAD + d]) + __half2float(Alo[tid * PAD + d]);
            s = fmaf(xv, xv, s);
        }
        rowN[tid] = sqrtf(s);
    }

    const uint32_t aRow = (uint32_t)((lane & 15) * PAD + (lane >> 4) * 8) * 2;
    const uint32_t aHiBase = sb + OFF_AHI + (uint32_t)(mblk * PAD * 2) + aRow;
    const uint32_t bLane = (uint32_t)(((lane & 7) + ((lane >> 4) << 3)) * PAD + (((lane >> 3) & 1) << 3)) * 2;
    const uint32_t bHiBase = sb + OFF_B + (uint32_t)(nblk * PAD * 2) + bLane;

    float acc[2][8][4];
#pragma unroll
    for (int mi = 0; mi < 2; mi++)
#pragma unroll
        for (int nt = 0; nt < 8; nt++)
#pragma unroll
            for (int j = 0; j < 4; j++) acc[mi][nt][j] = 0.f;

    // best-4 per owned row (4 rows per thread)
    float bv[16]; int bix[16];
#pragma unroll
    for (int i = 0; i < 16; i++) { bv[i] = 3.4e38f; bix[i] = 0x3fffffff; }

    for (int c = 0; c < NCHUNKS; c++) {
        __syncthreads();
        for (int j = tid; j < 1152; j += TPB) {   // hi-only chunk image
            int r = j / 9, s = j - r * 9;
            Bv[j] = *(const float4*)(g_cbh + c * CHUNK * PAD + r * PAD + s * 8);
        }
        __syncthreads();

#pragma unroll
        for (int ks = 0; ks < 4; ks++) {
            uint32_t ah[2][4];
#pragma unroll
            for (int mi = 0; mi < 2; mi++) {
                uint32_t ao = (uint32_t)(mi * 16 * PAD + ks * 16) * 2;
                LDSM_X4(ah[mi][0], ah[mi][1], ah[mi][2], ah[mi][3], aHiBase + ao);
            }
#pragma unroll
            for (int p = 0; p < 4; p++) {
                uint32_t bo = (uint32_t)(p * 16 * PAD + ks * 16) * 2;
                uint32_t bh0, bh1, bh2, bh3;
                LDSM_X4(bh0, bh1, bh2, bh3, bHiBase + bo);
#pragma unroll
                for (int mi = 0; mi < 2; mi++) {
                    MMA16816(acc[mi][2 * p + 0], ah[mi], bh0, bh1);
                    MMA16816(acc[mi][2 * p + 1], ah[mi], bh2, bh3);
                }
            }
        }

        const int cbase = c * CHUNK + nblk + 2 * (lane & 3);
#pragma unroll
        for (int nt = 0; nt < 8; nt++) {
            int col = cbase + nt * 8;
            float c20 = c2s[col], c21 = c2s[col + 1];
#pragma unroll
            for (int mi = 0; mi < 2; mi++)
#pragma unroll
                for (int h = 0; h < 2; h++) {
                    int rb = (mi * 2 + h) * 4;
                    float d0 = fmaf(-2.f, acc[mi][nt][h * 2 + 0], c20);
                    float d1 = fmaf(-2.f, acc[mi][nt][h * 2 + 1], c21);
                    ins4(bv + rb, bix + rb, d0, col);
                    ins4(bv + rb, bix + rb, d1, col + 1);
                    acc[mi][nt][h * 2 + 0] = 0.f;
                    acc[mi][nt][h * 2 + 1] = 0.f;
                }
        }
    }

    // dump candidates: slot = nb*4 + (lane&3), row per ridx
    const int slot = nb * 4 + (lane & 3);
#pragma unroll
    for (int ridx = 0; ridx < 4; ridx++) {
        int mi = ridx >> 1, h = ridx & 1;
        int row = mblk + mi * 16 + (lane >> 2) + h * 8;
#pragma unroll
        for (int j = 0; j < 4; j++)
            cand[(row * 8 + slot) * 4 + j] =
                make_uint2(__float_as_uint(bv[ridx * 4 + j]), (uint32_t)bix[ridx * 4 + j]);
    }
    __syncthreads();

    const float cmax = g_cmax;

    // per-row rescore (thread r handles row r)
    if (tid < BM) {
        const uint2* cr = cand + tid * 32;
        float mV = 3.4e38f;
#pragma unroll 4
        for (int j = 0; j < 32; j++) {
            float v = __uint_as_float(cr[j].x);
            if (v < mV) mV = v;
        }
        // |dist_approx - dist_exact| <= 2^-9 |x||c|; margin 2*(2^-8 |x| cmax + 1e-4) is 4x safe
        float wnd = mV + 2.f * (rowN[tid] * cmax * (1.f / 256.f) + 1e-4f);
        int fb = 0;
#pragma unroll
        for (int s = 0; s < 8; s++)     // each slot's 4th-best must clear the window
            if (__uint_as_float(cr[s * 4 + 3].x) <= wnd) fb = 1;
        fbflag[tid] = fb;
        if (!fb) {
            float bd = 3.4e38f; int bk = 0x3fffffff;
            for (int j = 0; j < 32; j++) {
                float v = __uint_as_float(cr[j].x);
                if (v <= wnd) {
                    int k = (int)cr[j].y;
                    float dot = 0.f;
                    const float* crow = cb + (size_t)k * D;
#pragma unroll
                    for (int d = 0; d < D; d++) {
                        float xv = __half2float(Ahi[tid * PAD + d]) + __half2float(Alo[tid * PAD + d]);
                        dot = fmaf(xv, __ldg(&crow[d]), dot);
                    }
                    float dd = fmaf(-2.f, dot, c2s[k]);
                    if (dd < bd || (dd == bd && k < bk)) { bd = dd; bk = k; }
                }
            }
            bestI[tid] = bk;
        }
    }
    __syncthreads();

    // fallback rows (rare): warp 0, cooperative exact full scan
    if (warp == 0) {
        for (int row = 0; row < BM; row++) {
            if (!fbflag[row]) continue;
            float bd = 3.4e38f; int bk = 0x3fffffff;
            for (int k = lane; k < KCODES; k += 32) {
                float dot = 0.f;
                const float* crow = cb + (size_t)k * D;
#pragma unroll
                for (int d = 0; d < D; d++) {
                    float xv = __half2float(Ahi[row * PAD + d]) + __half2float(Alo[row * PAD + d]);
                    dot = fmaf(xv, __ldg(&crow[d]), dot);
                }
                float dd = fmaf(-2.f, dot, c2s[k]);
                if (dd < bd || (dd == bd && k < bk)) { bd = dd; bk = k; }
            }
#pragma unroll
            for (int o = 16; o > 0; o >>= 1) {
                float ov = __shfl_down_sync(0xffffffffu, bd, o);
                int   ok = __shfl_down_sync(0xffffffffu, bk, o);
                if (ov < bd || (ov == bd && ok < bk)) { bd = ov; bk = ok; }
            }
            if (lane == 0) bestI[row] = bk;
        }
    }
    __syncthreads();

    if (tid < BM) {
        int gr = rowBase + tid;
        if (gr < N) {
            if (writeExtras) outT[gr] = (float)bestI[tid];
            atomicAdd(&g_counts[bestI[tid]], 1);
        }
    }
    __syncthreads();

    // quantized write + MSE
    float lsum = 0.f;
    for (int r = warp; r < BM; r += 8) {
        int gr = rowBase + r;
        if (gr >= N) continue;
        int bi = bestI[r];
        const float* crow = cb + (size_t)bi * D;
        float* qrow = outQ + (size_t)gr * D;
#pragma unroll
        for (int h = 0; h < 2; h++) {
            int d = h * 32 + lane;
            float cv = __ldg(&crow[d]);
            float xv = __half2float(Ahi[r * PAD + d]) + __half2float(Alo[r * PAD + d]);
            float diff = xv - cv;
            lsum = fmaf(diff, diff, lsum);
            qrow[d] = cv;
        }
    }
#pragma unroll
    for (int o = 16; o > 0; o >>= 1) lsum += __shfl_down_sync(0xffffffffu, lsum, o);
    if (lane == 0) wsum[warp] = lsum;
    __syncthreads();
    if (tid == 0) {
        float s = 0.f;
#pragma unroll
        for (int w = 0; w < 8; w++) s += wsum[w];
        atomicAdd(&g_mse_sum, (double)s);
    }
}

// ---------------- scalars ----------------
__global__ void vq_final(float* __restrict__ outS, int N) {
    const int tid = threadIdx.x;
    float ent = 0.f;
    for (int k = tid; k < 1024; k += blockDim.x) {
        float p = (float)g_counts[k] / (float)N;
        ent += p * logf(p + 1e-10f);
    }
#pragma unroll
    for (int o = 16; o > 0; o >>= 1) ent += __shfl_down_sync(0xffffffffu, ent, o);
    __shared__ float ws[32];
    const int warp = tid >> 5, lane = tid & 31;
    if (lane == 0) ws[warp] = ent;
    __syncthreads();
    if (tid == 0) {
        float e = 0.f;
        int nw = (blockDim.x + 31) >> 5;
        for (int w = 0; w < nw; w++) e += ws[w];
        float mse = (float)(g_mse_sum / ((double)N * (double)D));
        outS[0] = 1.25f * mse;
        outS[1] = 0.25f * mse;
        outS[2] = mse;
        outS[3] = expf(-e);
    }
}

extern "C" void kernel_launch(void* const* d_in, const int* in_sizes, int n_in,
                              void* d_out, int out_size)
{
    const float* x  = (const float*)d_in[0];
    const float* cb = (const float*)d_in[1];
    const int total = in_sizes[0];
    const int N = total / D;

    float* out = (float*)d_out;
    const int writeExtras = (out_size >= total + N + 4) ? 1 : 0;
    float* outQ = out;
    float* outT = writeExtras ? out + total : out;
    float* outS = writeExtras ? out + total + N : nullptr;

    cudaFuncSetAttribute(vq_main, cudaFuncAttributeMaxDynamicSharedMemorySize, SMEM_TOTAL);

    vq_prep<<<KCODES, D>>>(cb);
    vq_prep2<<<1, 1024>>>();
    const int grid = (N + BM - 1) / BM;
    vq_main<<<grid, TPB, SMEM_TOTAL>>>(x, cb, N, outQ, outT, writeExtras);
    if (writeExtras)
        vq_final<<<1, 1024>>>(outS, N);
}